// round 15
// baseline (speedup 1.0000x reference)
#include <cuda_runtime.h>

namespace {
constexpr int H = 128, Wd = 128;
constexpr int PLANE = H * Wd;                       // 16384
constexpr int NPLANES = 32 * 64;                    // 2048
constexpr long long TOTROWS = (long long)NPLANES * H;  // 262144
constexpr int THREADS = 160;                        // 5 warps/CTA
constexpr int CTAS_SM = 6;                          // 30 warps/SM @ 64 regs
constexpr int NBLK = 152 * CTAS_SM;                 // 912
constexpr int WPB = THREADS / 32;                   // 5
constexpr int NWARP = NBLK * WPB;                   // 4560 warp strips
}

struct RowS {
    float x[6];   // [0]=left edge, [1..4]=own 4 cols, [5]=right edge
    int   b[6];   // bins
};

__device__ __forceinline__ float4 ldrow(const float* __restrict__ xp, int r,
                                        int lane) {
    float4 v = make_float4(0.f, 0.f, 0.f, 0.f);
    if ((unsigned)r < (unsigned)H)
        v = __ldg(reinterpret_cast<const float4*>(xp + r * Wd + lane * 4));
    return v;
}

// Input is uniform [0,1): (int)(x*5) is already in [0,4]; no clamp needed.
// (Zero padding maps to bin 0.)
__device__ __forceinline__ int quant(float x) {
    return __float2int_rz(x * 5.0f);
}

// Quantize + edge exchange (2 MIO ops; edge bins recomputed on fma pipe).
__device__ __forceinline__ void build(float4 v, int lane, RowS& R) {
    R.x[1] = v.x; R.x[2] = v.y; R.x[3] = v.z; R.x[4] = v.w;
#pragma unroll
    for (int i = 1; i <= 4; ++i) R.b[i] = quant(R.x[i]);
    R.x[0] = __shfl_up_sync(0xffffffffu, v.w, 1);
    R.x[5] = __shfl_down_sync(0xffffffffu, v.x, 1);
    if (lane == 0)  R.x[0] = 0.f;   // x=0 kills the term; b irrelevant
    if (lane == 31) R.x[5] = 0.f;
    R.b[0] = quant(R.x[0]);
    R.b[5] = quant(R.x[5]);
}

__global__ __launch_bounds__(THREADS, CTAS_SM)
void col_kernel(const float* __restrict__ x,
                const float* __restrict__ Wp,
                const float* __restrict__ Lp,
                float* __restrict__ out) {
    // Bank-replicated WL table: addr = laneBase + bp*128 + bq*640 + o*3200.
    // Lane l only ever touches bank l -> conflict-free LDS.
    __shared__ float sWL[225 * 32];

    for (int t = threadIdx.x; t < 225 * 32; t += THREADS) {
        int idx = t >> 5;               // o*25 + bq*5 + bp
        int o  = idx / 25;
        int i  = idx - o * 25;          // bq*5 + bp (L row-major: L[bq][bp])
        sWL[t] = Wp[o] * Lp[i];
    }
    __syncthreads();

    const int lane = threadIdx.x & 31;
    const int gw   = blockIdx.x * WPB + (threadIdx.x >> 5);
    const char* laneBase = reinterpret_cast<const char*>(sWL) + lane * 4;

    // Contiguous global-row strip for this warp.
    long long gs = (long long)gw * TOTROWS / NWARP;
    long long ge = (long long)(gw + 1) * TOTROWS / NWARP;

    long long s = gs;
    while (s < ge) {
        const int p  = (int)(s >> 7);
        const int rs = (int)(s & 127);
        const int re = min(H, rs + (int)(ge - s));     // segment = one plane
        const float* xp = x + (size_t)p * PLANE;
        float* op = out + (size_t)p * PLANE;

        RowS Rr[3];
        float4 wv[3];
        build(ldrow(xp, rs - 1, lane), lane, Rr[0]);
        build(ldrow(xp, rs,     lane), lane, Rr[1]);
        wv[2] = ldrow(xp, rs + 1, lane);

        // 3-row blocks; 1-deep prefetch; all rotation indices static.
        for (int k = rs; k < re; k += 3) {
#pragma unroll
            for (int j = 0; j < 3; ++j) {
                const int r = k + j;
                wv[j] = ldrow(xp, r + 2, lane);            // prefetch
                build(wv[(j + 2) % 3], lane, Rr[(j + 2) % 3]);

                const RowS& A  = Rr[j % 3];
                const RowS& Bc = Rr[(j + 1) % 3];
                const RowS& Cn = Rr[(j + 2) % 3];

                float res[4];
#pragma unroll
                for (int i = 0; i < 4; ++i) {
                    const char* pb = laneBase + Bc.b[i + 1] * 128;
                    // Two accumulators: halve the serial FFMA chain.
                    float s0 = 0.f, s1 = 0.f;
#define COL_TERM(acc, R, o, dw)                                                \
                    acc += *reinterpret_cast<const float*>(                    \
                               pb + (R).b[i + (dw)] * 640 + (o) * 3200)        \
                           * (R).x[i + (dw)];
                    COL_TERM(s0, A,  0, 0) COL_TERM(s1, A,  1, 1)
                    COL_TERM(s0, A,  2, 2) COL_TERM(s1, Bc, 3, 0)
                    COL_TERM(s0, Bc, 4, 1) COL_TERM(s1, Bc, 5, 2)
                    COL_TERM(s0, Cn, 6, 0) COL_TERM(s1, Cn, 7, 1)
                    COL_TERM(s0, Cn, 8, 2)
#undef COL_TERM
                    res[i] = s0 + s1;
                }

                if (j == 0 || r < re) {
                    float4 o4 = make_float4(res[0], res[1], res[2], res[3]);
                    asm volatile(
                        "st.global.cs.v4.f32 [%0], {%1, %2, %3, %4};\n"
                        :: "l"(op + r * Wd + lane * 4),
                           "f"(o4.x), "f"(o4.y), "f"(o4.z), "f"(o4.w)
                        : "memory");
                }
            }
        }
        s += re - rs;
    }
}

extern "C" void kernel_launch(void* const* d_in, const int* in_sizes, int n_in,
                              void* d_out, int out_size) {
    const float* x = nullptr;
    const float* W = nullptr;
    const float* L = nullptr;
    for (int i = 0; i < n_in; ++i) {
        if (in_sizes[i] == 9)       W = (const float*)d_in[i];
        else if (in_sizes[i] == 25) L = (const float*)d_in[i];
        else                        x = (const float*)d_in[i];
    }
    col_kernel<<<NBLK, THREADS>>>(x, W, L, (float*)d_out);
}

// round 16
// speedup vs baseline: 1.0250x; 1.0250x over previous
#include <cuda_runtime.h>

namespace {
constexpr int H = 128, Wd = 128;
constexpr int PLANE = H * Wd;                       // 16384
constexpr int NPLANES = 32 * 64;                    // 2048
constexpr long long TOTROWS = (long long)NPLANES * H;  // 262144
constexpr int NBLK = 1216;                          // 2 waves of 4 CTAs/SM
constexpr int NWARP = NBLK * 8;                     // 9728 warp strips (~27 rows)
}

struct RowS {
    float x[6];   // [0]=left edge, [1..4]=own 4 cols, [5]=right edge
    int   b[6];   // bins
};

__device__ __forceinline__ float4 ldrow(const float* __restrict__ xp, int r,
                                        int lane) {
    float4 v = make_float4(0.f, 0.f, 0.f, 0.f);
    if ((unsigned)r < (unsigned)H)
        v = __ldg(reinterpret_cast<const float4*>(xp + r * Wd + lane * 4));
    return v;
}

// Input is uniform [0,1): (int)(x*5) is already in [0,4]; no clamp needed.
// (Zero padding maps to bin 0.)
__device__ __forceinline__ int quant(float x) {
    return __float2int_rz(x * 5.0f);
}

// Quantize + edge exchange (2 MIO ops; edge bins recomputed on fma pipe).
__device__ __forceinline__ void build(float4 v, int lane, RowS& R) {
    R.x[1] = v.x; R.x[2] = v.y; R.x[3] = v.z; R.x[4] = v.w;
#pragma unroll
    for (int i = 1; i <= 4; ++i) R.b[i] = quant(R.x[i]);
    R.x[0] = __shfl_up_sync(0xffffffffu, v.w, 1);
    R.x[5] = __shfl_down_sync(0xffffffffu, v.x, 1);
    if (lane == 0)  R.x[0] = 0.f;   // x=0 kills the term; b irrelevant
    if (lane == 31) R.x[5] = 0.f;
    R.b[0] = quant(R.x[0]);
    R.b[5] = quant(R.x[5]);
}

__global__ __launch_bounds__(256, 4)
void col_kernel(const float* __restrict__ x,
                const float* __restrict__ Wp,
                const float* __restrict__ Lp,
                float* __restrict__ out) {
    // Bank-replicated WL table: addr = laneBase + bp*128 + bq*640 + o*3200.
    // Lane l only ever touches bank l -> conflict-free LDS.
    __shared__ float sWL[225 * 32];

    for (int t = threadIdx.x; t < 225 * 32; t += 256) {
        int idx = t >> 5;               // o*25 + bq*5 + bp
        int o  = idx / 25;
        int i  = idx - o * 25;          // bq*5 + bp (L row-major: L[bq][bp])
        sWL[t] = Wp[o] * Lp[i];
    }
    __syncthreads();

    const int lane = threadIdx.x & 31;
    const int gw   = blockIdx.x * 8 + (threadIdx.x >> 5);
    const char* laneBase = reinterpret_cast<const char*>(sWL) + lane * 4;

    // Contiguous global-row strip for this warp.
    long long gs = (long long)gw * TOTROWS / NWARP;
    long long ge = (long long)(gw + 1) * TOTROWS / NWARP;

    long long s = gs;
    while (s < ge) {
        const int p  = (int)(s >> 7);
        const int rs = (int)(s & 127);
        const int re = min(H, rs + (int)(ge - s));     // segment = one plane
        const float* xp = x + (size_t)p * PLANE;
        float* op = out + (size_t)p * PLANE;

        RowS Rr[3];
        float4 wv[3];
        build(ldrow(xp, rs - 1, lane), lane, Rr[0]);
        build(ldrow(xp, rs,     lane), lane, Rr[1]);
        wv[2] = ldrow(xp, rs + 1, lane);

        // 3-row blocks; 1-deep prefetch; all rotation indices static.
        for (int k = rs; k < re; k += 3) {
#pragma unroll
            for (int j = 0; j < 3; ++j) {
                const int r = k + j;
                wv[j] = ldrow(xp, r + 2, lane);            // prefetch
                build(wv[(j + 2) % 3], lane, Rr[(j + 2) % 3]);

                const RowS& A  = Rr[j % 3];
                const RowS& Bc = Rr[(j + 1) % 3];
                const RowS& Cn = Rr[(j + 2) % 3];

                float res[4];
#pragma unroll
                for (int i = 0; i < 4; ++i) {
                    const char* pb = laneBase + Bc.b[i + 1] * 128;
                    // Two accumulators: halve the serial FFMA chain.
                    float s0 = 0.f, s1 = 0.f;
#define COL_TERM(acc, R, o, dw)                                                \
                    acc += *reinterpret_cast<const float*>(                    \
                               pb + (R).b[i + (dw)] * 640 + (o) * 3200)        \
                           * (R).x[i + (dw)];
                    COL_TERM(s0, A,  0, 0) COL_TERM(s1, A,  1, 1)
                    COL_TERM(s0, A,  2, 2) COL_TERM(s1, Bc, 3, 0)
                    COL_TERM(s0, Bc, 4, 1) COL_TERM(s1, Bc, 5, 2)
                    COL_TERM(s0, Cn, 6, 0) COL_TERM(s1, Cn, 7, 1)
                    COL_TERM(s0, Cn, 8, 2)
#undef COL_TERM
                    res[i] = s0 + s1;
                }

                if (j == 0 || r < re) {
                    float4 o4 = make_float4(res[0], res[1], res[2], res[3]);
                    asm volatile(
                        "st.global.cs.v4.f32 [%0], {%1, %2, %3, %4};\n"
                        :: "l"(op + r * Wd + lane * 4),
                           "f"(o4.x), "f"(o4.y), "f"(o4.z), "f"(o4.w)
                        : "memory");
                }
            }
        }
        s += re - rs;
    }
}

extern "C" void kernel_launch(void* const* d_in, const int* in_sizes, int n_in,
                              void* d_out, int out_size) {
    const float* x = nullptr;
    const float* W = nullptr;
    const float* L = nullptr;
    for (int i = 0; i < n_in; ++i) {
        if (in_sizes[i] == 9)       W = (const float*)d_in[i];
        else if (in_sizes[i] == 25) L = (const float*)d_in[i];
        else                        x = (const float*)d_in[i];
    }
    col_kernel<<<NBLK, 256>>>(x, W, L, (float*)d_out);
}